// round 15
// baseline (speedup 1.0000x reference)
#include <cuda_runtime.h>
#include <math.h>

#define NT    1024
#define NBLK  1024                 // one CTA per quarter-heatmap (aligned, uniform)
#define NHM   256
#define BIGI  0x7fffffff

__device__ float    g_S [NBLK];
__device__ float    g_WX[NBLK];
__device__ float    g_WY[NBLK];
__device__ float    g_TM[NBLK];
__device__ int      g_TI[NBLK];
__device__ unsigned g_count = 0;

__global__ __launch_bounds__(NT, 2)
void dsnt_uq_kernel(const float* __restrict__ inp, const float* __restrict__ tgt,
                    float* __restrict__ out) {
    const int b    = blockIdx.x;
    const int tid  = threadIdx.x;
    const int lane = tid & 31;
    const int warp = tid >> 5;

    const float4* __restrict__ in4 = (const float4*)inp;
    const float4* __restrict__ tg4 = (const float4*)tgt;

    __shared__ float shf[3][32];
    __shared__ float shm[32];
    __shared__ int   shi[32];
    __shared__ int   s_last;

    // quarter b: heatmap b>>2, quarter b&3 (64 rows); chunk/iter = 16 rows
    const unsigned base4 = ((unsigned)(b >> 2) << 14) + ((unsigned)(b & 3) << 12);
    const unsigned i0    = base4 + (unsigned)tid;

    const float c1 = (float)(((tid & 63) << 2) + 1);   // col+1, iteration-invariant
    const float r1 = (float)((tid >> 6) + 1);          // row-in-chunk + 1 (1..16)

    // ---- single fully-static branch-free sweep: 4 iterations (R7 body) ----
    float s = 0.f, sub = 0.f, sy = 0.f;
    float tmax  = -INFINITY;
    int   gbase = (int)i0;

    #pragma unroll
    for (int k = 0; k < 4; k++) {
        const unsigned i4 = i0 + (unsigned)(k * NT);
        float4 v = in4[i4];
        float4 t = tg4[i4];
        // inputs ~N(0,1): exp without max-subtraction is safe in fp32
        float e0 = __expf(v.x);
        float e1 = __expf(v.y);
        float e2 = __expf(v.z);
        float e3 = __expf(v.w);
        float rs = (e0 + e1) + (e2 + e3);
        s   += rs;
        sub += fmaf(3.f, e3, fmaf(2.f, e2, e1));   // sum j*e_j (j=0..3)
        sy   = fmaf(rs, (float)k, sy);             // sum k*rs
        // cheap group argmax (strict '>' keeps earliest group on ties)
        float gm = fmaxf(fmaxf(t.x, t.y), fmaxf(t.z, t.w));
        bool upd = gm > tmax;
        tmax  = fmaxf(tmax, gm);
        gbase = upd ? (int)i4 : gbase;
    }

    // resolve winning element index (first == match = first occurrence within group)
    int targ;
    {
        float4 t = tg4[gbase];
        int off = (t.x == tmax) ? 0 : (t.y == tmax) ? 1 : (t.z == tmax) ? 2 : 3;
        targ = (gbase << 2) + off;                 // global element index
    }

    const float rowb = (float)((b & 3) << 6);      // quarter's starting row
    float wx = fmaf(c1, s, sub);
    float wy = fmaf(rowb + r1, s, 16.f * sy);      // row stride 16 per iteration

    // ---- single block reduction (32 warps) ----
    #pragma unroll
    for (int off = 16; off > 0; off >>= 1) {
        s  += __shfl_xor_sync(0xffffffffu, s,  off);
        wx += __shfl_xor_sync(0xffffffffu, wx, off);
        wy += __shfl_xor_sync(0xffffffffu, wy, off);
        float ov = __shfl_xor_sync(0xffffffffu, tmax, off);
        int   oi = __shfl_xor_sync(0xffffffffu, targ, off);
        if (ov > tmax || (ov == tmax && oi < targ)) { tmax = ov; targ = oi; }
    }
    if (lane == 0) {
        shf[0][warp] = s; shf[1][warp] = wx; shf[2][warp] = wy;
        shm[warp] = tmax; shi[warp] = targ;
    }
    __syncthreads();
    if (warp == 0) {
        s    = shf[0][lane];
        wx   = shf[1][lane];
        wy   = shf[2][lane];
        tmax = shm[lane];
        targ = shi[lane];
        #pragma unroll
        for (int off = 16; off > 0; off >>= 1) {
            s  += __shfl_xor_sync(0xffffffffu, s,  off);
            wx += __shfl_xor_sync(0xffffffffu, wx, off);
            wy += __shfl_xor_sync(0xffffffffu, wy, off);
            float ov = __shfl_xor_sync(0xffffffffu, tmax, off);
            int   oi = __shfl_xor_sync(0xffffffffu, targ, off);
            if (ov > tmax || (ov == tmax && oi < targ)) { tmax = ov; targ = oi; }
        }
        if (lane == 0) {
            g_S [b] = s;  g_WX[b] = wx;  g_WY[b] = wy;
            g_TM[b] = tmax; g_TI[b] = targ;
            __threadfence();
            unsigned old = atomicAdd(&g_count, 1u);
            s_last = (old == NBLK - 1) ? 1 : 0;
        }
    }
    __syncthreads();

    // ---- globally-last CTA: combine 4 records per heatmap, finish loss ----
    if (s_last) {
        float ed = 0.f;
        if (tid < NHM) {
            const int r0 = tid << 2;
            float S = 0.f, WX = 0.f, WY = 0.f, TM = -INFINITY;
            int   TI = BIGI;
            #pragma unroll
            for (int j = 0; j < 4; j++) {          // ascending -> deterministic
                const int r = r0 + j;
                S  += __ldcg(&g_S [r]);
                WX += __ldcg(&g_WX[r]);
                WY += __ldcg(&g_WY[r]);
                float tm = __ldcg(&g_TM[r]);
                int   ti = __ldcg(&g_TI[r]);
                if (tm > TM || (tm == TM && ti < TI)) { TM = tm; TI = ti; }
            }
            const float inv    = 1.0f / (S * 256.f);
            const float pred_x = WX * inv;
            const float pred_y = WY * inv;
            const float true_x = (float)((TI & 255) + 1)        * (1.0f / 256.f);
            const float true_y = (float)(((TI >> 8) & 255) + 1) * (1.0f / 256.f);
            const float dx = true_x - pred_x;
            const float dy = true_y - pred_y;
            ed = sqrtf(dx * dx + dy * dy);
        }
        #pragma unroll
        for (int off = 16; off > 0; off >>= 1)
            ed += __shfl_xor_sync(0xffffffffu, ed, off);
        if (lane == 0) shm[warp] = ed;
        __syncthreads();
        if (tid == 0) {
            float tot = 0.f;
            #pragma unroll
            for (int w = 0; w < 8; w++) tot += shm[w];   // warps 0..7 hold tid<256
            out[0]  = tot * (1.0f / 32.f);   // divide by batch B=32
            g_count = 0;                     // reset for next graph replay
        }
    }
}

extern "C" void kernel_launch(void* const* d_in, const int* in_sizes, int n_in,
                              void* d_out, int out_size) {
    const float* inp = (const float*)d_in[0];
    const float* tgt = (const float*)d_in[1];
    dsnt_uq_kernel<<<NBLK, NT>>>(inp, tgt, (float*)d_out);
}

// round 16
// speedup vs baseline: 1.0268x; 1.0268x over previous
#include <cuda_runtime.h>
#include <math.h>

#define NT     1024
#define NFULL  136                 // bids 0..135: full heatmaps 0..135 (16 iters)
#define NTQ    160                 // bids 136..295: 3 strided quarters each (12 iters)
#define NBLK   296                 // 148 SMs x occ 2 -> one wave, pairs (i, i+148)
#define NPOOL  480                 // quarters of heatmaps 136..255
#define NHM    256
#define BIGI   0x7fffffff

__device__ float    g_ed[NFULL];   // full CTAs write distance directly
__device__ float    g_S [NPOOL];
__device__ float    g_WX[NPOOL];
__device__ float    g_WY[NPOOL];
__device__ float    g_TM[NPOOL];
__device__ int      g_TI[NPOOL];
__device__ unsigned g_count = 0;

struct Red { float s, wx, wy, tm; int ti; };

// fully-static branch-free sweep (R7 body) over ITERS*1024 float4 from base4
template <int ITERS>
__device__ __forceinline__ void sweep(
    const float4* __restrict__ in4, const float4* __restrict__ tg4,
    unsigned base4, int tid,
    float& s, float& sub, float& sy, float& tmax, int& gbase)
{
    const unsigned i0 = base4 + (unsigned)tid;
    s = 0.f; sub = 0.f; sy = 0.f;
    tmax = -INFINITY; gbase = (int)i0;
    #pragma unroll
    for (int k = 0; k < ITERS; k++) {
        const unsigned i4 = i0 + (unsigned)(k * NT);
        float4 v = in4[i4];
        float4 t = tg4[i4];
        // inputs ~N(0,1): exp without max-subtraction is safe in fp32
        float e0 = __expf(v.x);
        float e1 = __expf(v.y);
        float e2 = __expf(v.z);
        float e3 = __expf(v.w);
        float rs = (e0 + e1) + (e2 + e3);
        s   += rs;
        sub += fmaf(3.f, e3, fmaf(2.f, e2, e1));   // sum j*e_j (j=0..3)
        sy   = fmaf(rs, (float)k, sy);             // sum k*rs
        // cheap group argmax (strict '>' keeps earliest group on ties)
        float gm = fmaxf(fmaxf(t.x, t.y), fmaxf(t.z, t.w));
        bool upd = gm > tmax;
        tmax  = fmaxf(tmax, gm);
        gbase = upd ? (int)i4 : gbase;
    }
}

// fold coefficients + resolve argmax element (first == match = first occurrence)
__device__ __forceinline__ Red finish(
    const float4* __restrict__ tg4, int tid, float rowb,
    float s, float sub, float sy, float tmax, int gbase)
{
    float4 t = tg4[gbase];
    int off = (t.x == tmax) ? 0 : (t.y == tmax) ? 1 : (t.z == tmax) ? 2 : 3;
    const float c1 = (float)(((tid & 63) << 2) + 1);
    const float r1 = (float)((tid >> 6) + 1);
    Red r;
    r.s  = s;
    r.wx = fmaf(c1, s, sub);
    r.wy = fmaf(rowb + r1, s, 16.f * sy);
    r.tm = tmax;
    r.ti = (gbase << 2) + off;     // global element index
    return r;
}

// block reduction; returns true on tid 0 with totals in r (leading sync: shared reuse)
__device__ __forceinline__ bool block_reduce(
    Red& r, float (*shf)[32], float* shm, int* shi, int lane, int warp)
{
    __syncthreads();
    #pragma unroll
    for (int off = 16; off > 0; off >>= 1) {
        r.s  += __shfl_xor_sync(0xffffffffu, r.s,  off);
        r.wx += __shfl_xor_sync(0xffffffffu, r.wx, off);
        r.wy += __shfl_xor_sync(0xffffffffu, r.wy, off);
        float ov = __shfl_xor_sync(0xffffffffu, r.tm, off);
        int   oi = __shfl_xor_sync(0xffffffffu, r.ti, off);
        if (ov > r.tm || (ov == r.tm && oi < r.ti)) { r.tm = ov; r.ti = oi; }
    }
    if (lane == 0) {
        shf[0][warp] = r.s; shf[1][warp] = r.wx; shf[2][warp] = r.wy;
        shm[warp] = r.tm; shi[warp] = r.ti;
    }
    __syncthreads();
    if (warp == 0) {
        r.s  = shf[0][lane]; r.wx = shf[1][lane]; r.wy = shf[2][lane];
        r.tm = shm[lane];    r.ti = shi[lane];
        #pragma unroll
        for (int off = 16; off > 0; off >>= 1) {
            r.s  += __shfl_xor_sync(0xffffffffu, r.s,  off);
            r.wx += __shfl_xor_sync(0xffffffffu, r.wx, off);
            r.wy += __shfl_xor_sync(0xffffffffu, r.wy, off);
            float ov = __shfl_xor_sync(0xffffffffu, r.tm, off);
            int   oi = __shfl_xor_sync(0xffffffffu, r.ti, off);
            if (ov > r.tm || (ov == r.tm && oi < r.ti)) { r.tm = ov; r.ti = oi; }
        }
        return lane == 0;
    }
    return false;
}

__global__ __launch_bounds__(NT, 2)
void dsnt_strided_kernel(const float* __restrict__ inp, const float* __restrict__ tgt,
                         float* __restrict__ out) {
    const int b    = blockIdx.x;
    const int tid  = threadIdx.x;
    const int lane = tid & 31;
    const int warp = tid >> 5;

    const float4* __restrict__ in4 = (const float4*)inp;
    const float4* __restrict__ tg4 = (const float4*)tgt;

    __shared__ float shf[3][32];
    __shared__ float shm[32];
    __shared__ int   shi[32];
    __shared__ int   s_last;
    // per-thread stash for sweep 0/1 records (own slot -> no sync needed)
    __shared__ float stf[2][4][NT];
    __shared__ int   sti[2][NT];

    float s, sub, sy, tmax; int gbase;

    if (b < NFULL) {
        // ---- full heatmap b: exact R7 path ----
        sweep<16>(in4, tg4, (unsigned)b << 14, tid, s, sub, sy, tmax, gbase);
        Red r = finish(tg4, tid, 0.f, s, sub, sy, tmax, gbase);
        if (block_reduce(r, shf, shm, shi, lane, warp)) {
            const float inv    = 1.0f / (r.s * 256.f);
            const float pred_x = r.wx * inv;
            const float pred_y = r.wy * inv;
            const float true_x = (float)((r.ti & 255) + 1)        * (1.0f / 256.f);
            const float true_y = (float)(((r.ti >> 8) & 255) + 1) * (1.0f / 256.f);
            const float dx = true_x - pred_x;
            const float dy = true_y - pred_y;
            g_ed[b] = sqrtf(dx * dx + dy * dy);
        }
    } else {
        // ---- 3 strided aligned quarters: pool p = u + 160*j, global quarter 544+p ----
        const int u = b - NFULL;
        // sweeps back-to-back, straight-line, no barriers between; stash 0/1 to smem
        #pragma unroll
        for (int j = 0; j < 2; j++) {
            const int p = u + 160 * j;
            sweep<4>(in4, tg4, (unsigned)(544 + p) << 12, tid, s, sub, sy, tmax, gbase);
            Red r = finish(tg4, tid, (float)((p & 3) << 6), s, sub, sy, tmax, gbase);
            stf[j][0][tid] = r.s;  stf[j][1][tid] = r.wx;
            stf[j][2][tid] = r.wy; stf[j][3][tid] = r.tm;
            sti[j][tid]    = r.ti;
        }
        const int p2 = u + 320;
        sweep<4>(in4, tg4, (unsigned)(544 + p2) << 12, tid, s, sub, sy, tmax, gbase);
        Red r2 = finish(tg4, tid, (float)((p2 & 3) << 6), s, sub, sy, tmax, gbase);

        // all loads issued; now the three reductions
        if (block_reduce(r2, shf, shm, shi, lane, warp)) {
            g_S[p2] = r2.s; g_WX[p2] = r2.wx; g_WY[p2] = r2.wy;
            g_TM[p2] = r2.tm; g_TI[p2] = r2.ti;
        }
        #pragma unroll
        for (int j = 1; j >= 0; j--) {
            Red r;
            r.s  = stf[j][0][tid]; r.wx = stf[j][1][tid];
            r.wy = stf[j][2][tid]; r.tm = stf[j][3][tid];
            r.ti = sti[j][tid];
            const int p = u + 160 * j;
            if (block_reduce(r, shf, shm, shi, lane, warp)) {
                g_S[p] = r.s; g_WX[p] = r.wx; g_WY[p] = r.wy;
                g_TM[p] = r.tm; g_TI[p] = r.ti;
            }
        }
    }

    __syncthreads();
    if (tid == 0) {
        __threadfence();                   // tid0 performed all global writes above
        unsigned old = atomicAdd(&g_count, 1u);
        s_last = (old == NBLK - 1) ? 1 : 0;
    }
    __syncthreads();

    // ---- globally-last CTA: combine donor records, reduce 256 distances ----
    if (s_last) {
        float ed = 0.f;
        if (tid < NFULL) {
            ed = __ldcg(&g_ed[tid]);
        } else if (tid < NHM) {
            const int p0 = (tid - NFULL) << 2;     // donor's 4 pool quarters
            float S = 0.f, WX = 0.f, WY = 0.f, TM = -INFINITY;
            int   TI = BIGI;
            #pragma unroll
            for (int j = 0; j < 4; j++) {          // ascending -> deterministic
                const int p = p0 + j;
                S  += __ldcg(&g_S [p]);
                WX += __ldcg(&g_WX[p]);
                WY += __ldcg(&g_WY[p]);
                float tm = __ldcg(&g_TM[p]);
                int   ti = __ldcg(&g_TI[p]);
                if (tm > TM || (tm == TM && ti < TI)) { TM = tm; TI = ti; }
            }
            const float inv    = 1.0f / (S * 256.f);
            const float pred_x = WX * inv;
            const float pred_y = WY * inv;
            const float true_x = (float)((TI & 255) + 1)        * (1.0f / 256.f);
            const float true_y = (float)(((TI >> 8) & 255) + 1) * (1.0f / 256.f);
            const float dx = true_x - pred_x;
            const float dy = true_y - pred_y;
            ed = sqrtf(dx * dx + dy * dy);
        }
        #pragma unroll
        for (int off = 16; off > 0; off >>= 1)
            ed += __shfl_xor_sync(0xffffffffu, ed, off);
        if (lane == 0) shm[warp] = ed;
        __syncthreads();
        if (tid == 0) {
            float tot = 0.f;
            #pragma unroll
            for (int w = 0; w < 8; w++) tot += shm[w];   // warps 0..7 hold tid<256
            out[0]  = tot * (1.0f / 32.f);   // divide by batch B=32
            g_count = 0;                     // reset for next graph replay
        }
    }
}

extern "C" void kernel_launch(void* const* d_in, const int* in_sizes, int n_in,
                              void* d_out, int out_size) {
    const float* inp = (const float*)d_in[0];
    const float* tgt = (const float*)d_in[1];
    dsnt_strided_kernel<<<NBLK, NT>>>(inp, tgt, (float*)d_out);
}

// round 17
// speedup vs baseline: 1.0850x; 1.0567x over previous
#include <cuda_runtime.h>
#include <math.h>

#define WIDTH   256
#define HW      65536
#define NHM     256        // B*C heatmaps
#define NT      1024
#define NV      16         // float4 groups per thread: HW/4/NT

__device__ float    g_ed[NHM];
__device__ unsigned g_count = 0;

__global__ __launch_bounds__(NT, 2)
void dsnt_split_kernel(const float* __restrict__ inp, const float* __restrict__ tgt,
                       float* __restrict__ out) {
    const int hm   = blockIdx.x;
    const float4* __restrict__ in4 = (const float4*)inp + (size_t)hm * (HW / 4);
    const float4* __restrict__ tg4 = (const float4*)tgt + (size_t)hm * (HW / 4);
    const int tid  = threadIdx.x;
    const int lane = tid & 31;
    const int warp = tid >> 5;

    __shared__ float sh[4][32];
    __shared__ int   shi[32];
    __shared__ int   s_last;

    // ---------- Loop 1: target argmax (tiny body -> deep load batching) ----------
    float tmax  = -INFINITY;
    int   kbest = 0;
    #pragma unroll
    for (int k = 0; k < NV; k++) {
        float4 t = tg4[tid + k * NT];
        // cheap group argmax: strict '>' keeps earliest group on ties
        float gm = fmaxf(fmaxf(t.x, t.y), fmaxf(t.z, t.w));
        bool upd = gm > tmax;
        tmax  = fmaxf(tmax, gm);
        kbest = upd ? k : kbest;                    // SEL with immediate
    }

    // resolve winning element (first == match = first occurrence within group);
    // this dependent load's latency hides under the input loop below
    const int gbase = tid + kbest * NT;
    float4 tw = tg4[gbase];

    // ---------- Loop 2: input exp + weighted sums (no target regs live) ----------
    float s = 0.f, sub = 0.f, sy = 0.f;
    #pragma unroll
    for (int k = 0; k < NV; k++) {
        float4 v = in4[tid + k * NT];
        // inputs ~N(0,1): exp without max-subtraction is safe in fp32
        float e0 = __expf(v.x);
        float e1 = __expf(v.y);
        float e2 = __expf(v.z);
        float e3 = __expf(v.w);
        float rs = (e0 + e1) + (e2 + e3);
        s   += rs;
        sub += fmaf(3.f, e3, fmaf(2.f, e2, e1));    // sum j*e_j (j=0..3)
        sy   = fmaf(rs, (float)k, sy);              // sum k*rs
    }

    int targ;
    {
        int off = (tw.x == tmax) ? 0 : (tw.y == tmax) ? 1 : (tw.z == tmax) ? 2 : 3;
        targ = (gbase << 2) + off;                  // heatmap-local element index
    }

    // per-thread unnormalized coordinate sums
    // col0 = (tid*4) & 255 is k-invariant; row = (tid>>6) + 16k
    const float c1 = (float)(((tid & 63) << 2) + 1);
    const float r1 = (float)((tid >> 6) + 1);
    float wx = fmaf(c1, s, sub);
    float wy = fmaf(r1, s, 16.f * sy);

    // ---- combined block reduction: (s, wx, wy) sum + (tmax, targ) argmax ----
    #pragma unroll
    for (int off = 16; off > 0; off >>= 1) {
        s  += __shfl_xor_sync(0xffffffffu, s,  off);
        wx += __shfl_xor_sync(0xffffffffu, wx, off);
        wy += __shfl_xor_sync(0xffffffffu, wy, off);
        float ov = __shfl_xor_sync(0xffffffffu, tmax, off);
        int   oi = __shfl_xor_sync(0xffffffffu, targ, off);
        if (ov > tmax || (ov == tmax && oi < targ)) { tmax = ov; targ = oi; }
    }
    if (lane == 0) {
        sh[0][warp] = s; sh[1][warp] = wx; sh[2][warp] = wy;
        sh[3][warp] = tmax; shi[warp] = targ;
    }
    __syncthreads();
    if (warp == 0) {
        s    = sh[0][lane];
        wx   = sh[1][lane];
        wy   = sh[2][lane];
        tmax = sh[3][lane];
        targ = shi[lane];
        #pragma unroll
        for (int off = 16; off > 0; off >>= 1) {
            s  += __shfl_xor_sync(0xffffffffu, s,  off);
            wx += __shfl_xor_sync(0xffffffffu, wx, off);
            wy += __shfl_xor_sync(0xffffffffu, wy, off);
            float ov = __shfl_xor_sync(0xffffffffu, tmax, off);
            int   oi = __shfl_xor_sync(0xffffffffu, targ, off);
            if (ov > tmax || (ov == tmax && oi < targ)) { tmax = ov; targ = oi; }
        }
    }

    // ---- tid 0: per-heatmap distance, then last-block detection ----
    if (tid == 0) {
        const float inv    = 1.0f / (s * (float)WIDTH);   // W == H == 256
        const float pred_x = wx * inv;
        const float pred_y = wy * inv;
        const float true_x = (float)((targ & 255) + 1) * (1.0f / 256.f);
        const float true_y = (float)((targ >> 8)  + 1) * (1.0f / 256.f);
        const float dx = true_x - pred_x;
        const float dy = true_y - pred_y;
        g_ed[hm] = sqrtf(dx * dx + dy * dy);
        __threadfence();
        unsigned old = atomicAdd(&g_count, 1u);
        s_last = (old == NHM - 1) ? 1 : 0;
    }
    __syncthreads();

    // ---- last block: reduce 256 distances, write scalar, reset counter ----
    if (s_last) {
        float v = (tid < NHM) ? __ldcg(&g_ed[tid]) : 0.f;
        #pragma unroll
        for (int off = 16; off > 0; off >>= 1)
            v += __shfl_xor_sync(0xffffffffu, v, off);
        if (lane == 0 && tid < NHM) sh[0][warp] = v;   // warps 0..7
        __syncthreads();
        if (tid == 0) {
            float tot = 0.f;
            #pragma unroll
            for (int w = 0; w < 8; w++) tot += sh[0][w];
            out[0]  = tot * (1.0f / 32.f);   // divide by batch B=32
            g_count = 0;                     // reset for next graph replay
        }
    }
}

extern "C" void kernel_launch(void* const* d_in, const int* in_sizes, int n_in,
                              void* d_out, int out_size) {
    const float* inp = (const float*)d_in[0];
    const float* tgt = (const float*)d_in[1];
    dsnt_split_kernel<<<NHM, NT>>>(inp, tgt, (float*)d_out);
}